// round 7
// baseline (speedup 1.0000x reference)
#include <cuda_runtime.h>
#include <cstdint>
#include <math.h>

#define Bz   32
#define SQ   2048
#define SKV  2048
#define Dd   128
#define BM   64
#define BN   128
#define NT   256

#define QS 68      // sQt stride [d][row64]
#define KS 132     // sKt stride [d][kv128]
#define VS 132     // sV  stride [n][d128]
#define PS 68      // sPt stride [col128][row64]

typedef unsigned long long u64;
typedef unsigned int u32;

// 32 MB static: K pre-transposed to [B][D][SKV]
__device__ float g_kt[(size_t)Bz * Dd * SKV];

// ---------------- f32x2 packed helpers ----------------
__device__ __forceinline__ u64 ffma2(u64 a, u64 b, u64 c) {
    u64 d; asm("fma.rn.f32x2 %0, %1, %2, %3;" : "=l"(d) : "l"(a), "l"(b), "l"(c));
    return d;
}
__device__ __forceinline__ u64 fmul2(u64 a, u64 b) {
    u64 d; asm("mul.rn.f32x2 %0, %1, %2;" : "=l"(d) : "l"(a), "l"(b));
    return d;
}
__device__ __forceinline__ u64 pk2(float lo, float hi) {
    u64 d; asm("mov.b64 %0, {%1, %2};" : "=l"(d)
               : "r"(__float_as_uint(lo)), "r"(__float_as_uint(hi)));
    return d;
}
__device__ __forceinline__ void upk2(u64 v, float& lo, float& hi) {
    u32 a, b; asm("mov.b64 {%0, %1}, %2;" : "=r"(a), "=r"(b) : "l"(v));
    lo = __uint_as_float(a); hi = __uint_as_float(b);
}

// ---------------- cp.async helpers ----------------
__device__ __forceinline__ void cpa16(u32 dst, const float* src) {
    asm volatile("cp.async.cg.shared.global [%0], [%1], 16;" :: "r"(dst), "l"(src));
}
#define CP_COMMIT() asm volatile("cp.async.commit_group;" ::: "memory")
#define CP_WAIT0()  asm volatile("cp.async.wait_group 0;" ::: "memory")
#define CP_WAIT1()  asm volatile("cp.async.wait_group 1;" ::: "memory")

// ---------------- Threefry-2x32-20, key=(0,42) ----------------
__device__ __forceinline__ void threefry_0_42(u32 x0, u32 x1, u32& y0, u32& y1) {
    const u32 ks1 = 42u;
    const u32 ks2 = 0x1BD11BDAu ^ 42u;
    x1 += ks1;
#define TF_R(r) { x0 += x1; x1 = __funnelshift_l(x1, x1, (r)); x1 ^= x0; }
    TF_R(13) TF_R(15) TF_R(26) TF_R(6)
    x0 += ks1; x1 += ks2 + 1u;
    TF_R(17) TF_R(29) TF_R(16) TF_R(24)
    x0 += ks2; x1 += 2u;
    TF_R(13) TF_R(15) TF_R(26) TF_R(6)
    x0 += 0u;  x1 += ks1 + 3u;
    TF_R(17) TF_R(29) TF_R(16) TF_R(24)
    x0 += ks1; x1 += ks2 + 4u;
    TF_R(13) TF_R(15) TF_R(26) TF_R(6)
    x0 += ks2; x1 += 5u;
#undef TF_R
    y0 = x0; y1 = x1;
}
// keep <=> fp32-uniform(bits) < 0.7  <=>  bits < (5872026 << 9)   (exact)
#define KEEP_THRESH 3006477312u

// ---------------------------------------------------------------------------
// K transpose: g_kt[b][d][s] = k[b][s][d]
// ---------------------------------------------------------------------------
__global__ __launch_bounds__(256, 4) void transpose_k_kernel(const float* __restrict__ k) {
    __shared__ float t[32][33];
    int b  = blockIdx.z;
    int s0 = blockIdx.x << 5;
    int d0 = blockIdx.y << 5;
    const float* kb = k + ((size_t)b * SKV + s0) * Dd + d0;
#pragma unroll
    for (int r = threadIdx.y; r < 32; r += 8)
        t[r][threadIdx.x] = kb[r * Dd + threadIdx.x];
    __syncthreads();
    float* kt = g_kt + ((size_t)b * Dd + d0) * SKV + s0;
#pragma unroll
    for (int r = threadIdx.y; r < 32; r += 8)
        kt[r * SKV + threadIdx.x] = t[threadIdx.x][r];
}

// ---------------------------------------------------------------------------
// Flash attention, fp32 FFMA2, threefry fused into QK, cp.async K/V pipeline.
// CTA = (batch b, 64 q rows). 256 threads: tm = tid>>5 (0..7), tn = tid&31.
// Thread: S rows 8tm+i (i<8), S cols 4tn+j (j<4); O cols 4tn+j.
// ---------------------------------------------------------------------------
__global__ __launch_bounds__(NT, 1) void attn_kernel(
    const float* __restrict__ q, const float* __restrict__ v,
    const float* __restrict__ sf, float* __restrict__ out) {

    extern __shared__ float sm[];
    float* sQt = sm;                    // [128][QS]
    float* sKt = sQt + Dd * QS;         // [128][KS]  d-major, from g_kt
    float* sV  = sKt + Dd * KS;         // [128][VS]
    float* sPt = sV + BN * VS;          // [128][PS]  P^T masked

    const int tid = threadIdx.x;
    const int tm  = tid >> 5;           // 0..7
    const int tn  = tid & 31;           // 0..31
    const int b   = blockIdx.y;
    const int q0  = blockIdx.x * BM;
    const float scale = sf[b];

    const float* ktb = g_kt + (size_t)b * Dd * SKV;     // [d][s]
    const float* vb  = v + (size_t)b * SKV * Dd;        // [s][d]

    // ---- prologue: start K(0) copy ----
    {
        u32 dK = (u32)__cvta_generic_to_shared(sKt);
#pragma unroll
        for (int it = 0; it < 16; ++it) {
            int id = it * NT + tid;             // 0..4095
            int d  = id >> 5;                   // 0..127
            int c  = (id & 31) << 2;            // float offset
            cpa16(dK + (u32)(d * KS + c) * 4u, ktb + (size_t)d * SKV + 0 + c);
        }
        CP_COMMIT();
    }

    // ---- stage Q (once), transposed + pre-scaled ----
    {
        const float* qb = q + ((size_t)b * SQ + q0) * Dd;
#pragma unroll
        for (int it = 0; it < 32; ++it) {
            int idx = it * NT + tid;            // 0..8191
            int r = idx >> 7;                   // 0..63
            int d = idx & 127;
            sQt[d * QS + r] = qb[idx] * scale;
        }
    }

    u64 acc[4][4];
    float m_i[8], l_i[8];
#pragma unroll
    for (int ip = 0; ip < 4; ++ip)
#pragma unroll
        for (int j = 0; j < 4; ++j) acc[ip][j] = 0ull;
#pragma unroll
    for (int i = 0; i < 8; ++i) { m_i[i] = -INFINITY; l_i[i] = 0.f; }

    u32 dV = (u32)__cvta_generic_to_shared(sV);
    u32 dK = (u32)__cvta_generic_to_shared(sKt);

    const u32 eBase0 = ((u32)(b * SQ + q0 + (tm << 3))) * (u32)SKV + (u32)(tn << 2);

    for (int kv0 = 0; kv0 < SKV; kv0 += BN) {
        // K(i) landed (only it may be pending at this point)
        CP_WAIT0();
        __syncthreads();        // K visible to all; prev PV done -> sV free

        // issue V(i); waited before PV (hidden by QK)
        {
#pragma unroll
            for (int it = 0; it < 16; ++it) {
                int id = it * NT + tid;
                int r  = id >> 5;
                int c  = (id & 31) << 2;
                cpa16(dV + (u32)(r * VS + c) * 4u,
                      vb + (size_t)(kv0 + r) * Dd + c);
            }
            CP_COMMIT();
        }

        // ---- S = Q@K^T via FFMA2, with threefry fused (1 hash per 4 d) ----
        u64 s2[4][4];
#pragma unroll
        for (int ip = 0; ip < 4; ++ip)
#pragma unroll
            for (int j = 0; j < 4; ++j) s2[ip][j] = 0ull;

        u32 mbits = 0;                          // bit (i*4+j) = keep p[i][j]
        const u32 eBase = eBase0 + (u32)kv0;

#pragma unroll 2
        for (int g = 0; g < 32; ++g) {
            // threefry hash for bit g: row i=g>>2, col j=g&3
            {
                u32 y0, y1;
                u32 e = eBase + ((u32)(g >> 2) << 11) + (u32)(g & 3);
                threefry_0_42(0u, e, y0, y1);
                mbits |= (u32)((y0 ^ y1) < KEEP_THRESH) << g;
            }
#pragma unroll
            for (int dq = 0; dq < 4; ++dq) {
                int d = (g << 2) + dq;
                ulonglong2 qv = *(const ulonglong2*)(sQt + d * QS + (tm << 3));
                ulonglong2 qw = *(const ulonglong2*)(sQt + d * QS + (tm << 3) + 4);
                u64 q01 = qv.x, q23 = qv.y, q45 = qw.x, q67 = qw.y;
                float4 kf = *(const float4*)(sKt + d * KS + (tn << 2));
                u64 k0 = pk2(kf.x, kf.x), k1 = pk2(kf.y, kf.y);
                u64 k2 = pk2(kf.z, kf.z), k3 = pk2(kf.w, kf.w);
                s2[0][0] = ffma2(q01, k0, s2[0][0]);
                s2[0][1] = ffma2(q01, k1, s2[0][1]);
                s2[0][2] = ffma2(q01, k2, s2[0][2]);
                s2[0][3] = ffma2(q01, k3, s2[0][3]);
                s2[1][0] = ffma2(q23, k0, s2[1][0]);
                s2[1][1] = ffma2(q23, k1, s2[1][1]);
                s2[1][2] = ffma2(q23, k2, s2[1][2]);
                s2[1][3] = ffma2(q23, k3, s2[1][3]);
                s2[2][0] = ffma2(q45, k0, s2[2][0]);
                s2[2][1] = ffma2(q45, k1, s2[2][1]);
                s2[2][2] = ffma2(q45, k2, s2[2][2]);
                s2[2][3] = ffma2(q45, k3, s2[2][3]);
                s2[3][0] = ffma2(q67, k0, s2[3][0]);
                s2[3][1] = ffma2(q67, k1, s2[3][1]);
                s2[3][2] = ffma2(q67, k2, s2[3][2]);
                s2[3][3] = ffma2(q67, k3, s2[3][3]);
            }
        }

        // ---- online softmax ----
        float p[8][4];
#pragma unroll
        for (int ip = 0; ip < 4; ++ip)
#pragma unroll
            for (int j = 0; j < 4; ++j)
                upk2(s2[ip][j], p[2 * ip][j], p[2 * ip + 1][j]);

        float fac[8];
#pragma unroll
        for (int i = 0; i < 8; ++i) {
            float mx = fmaxf(fmaxf(p[i][0], p[i][1]), fmaxf(p[i][2], p[i][3]));
#pragma unroll
            for (int off = 16; off >= 1; off >>= 1)
                mx = fmaxf(mx, __shfl_xor_sync(0xffffffffu, mx, off));
            float mnew = fmaxf(m_i[i], mx);
            fac[i] = __expf(m_i[i] - mnew);
            m_i[i] = mnew;
            float rs = 0.f;
#pragma unroll
            for (int j = 0; j < 4; ++j) {
                p[i][j] = __expf(p[i][j] - mnew);
                rs += p[i][j];
            }
#pragma unroll
            for (int off = 16; off >= 1; off >>= 1)
                rs += __shfl_xor_sync(0xffffffffu, rs, off);
            l_i[i] = l_i[i] * fac[i] + rs;
        }
#pragma unroll
        for (int ip = 0; ip < 4; ++ip) {
            u64 f2 = pk2(fac[2 * ip], fac[2 * ip + 1]);
#pragma unroll
            for (int j = 0; j < 4; ++j) acc[ip][j] = fmul2(acc[ip][j], f2);
        }

        // ---- write masked P^T (apply keep bits) ----
#pragma unroll
        for (int j = 0; j < 4; ++j) {
            int c = (tn << 2) + j;
            float4 w0, w1;
            w0.x = (mbits >> (0 + j)) & 1u  ? p[0][j] : 0.f;
            w0.y = (mbits >> (4 + j)) & 1u  ? p[1][j] : 0.f;
            w0.z = (mbits >> (8 + j)) & 1u  ? p[2][j] : 0.f;
            w0.w = (mbits >> (12 + j)) & 1u ? p[3][j] : 0.f;
            w1.x = (mbits >> (16 + j)) & 1u ? p[4][j] : 0.f;
            w1.y = (mbits >> (20 + j)) & 1u ? p[5][j] : 0.f;
            w1.z = (mbits >> (24 + j)) & 1u ? p[6][j] : 0.f;
            w1.w = (mbits >> (28 + j)) & 1u ? p[7][j] : 0.f;
            *(float4*)(sPt + c * PS + (tm << 3)) = w0;
            *(float4*)(sPt + c * PS + (tm << 3) + 4) = w1;
        }
        __syncthreads();        // all QK reads of sKt done; P visible

        // issue K(i+1) into sKt (hidden by PV)
        if (kv0 + BN < SKV) {
#pragma unroll
            for (int it = 0; it < 16; ++it) {
                int id = it * NT + tid;
                int d  = id >> 5;
                int c  = (id & 31) << 2;
                cpa16(dK + (u32)(d * KS + c) * 4u,
                      ktb + (size_t)d * SKV + (kv0 + BN) + c);
            }
            CP_COMMIT();
            CP_WAIT1();         // V(i) done; K(i+1) may fly
        } else {
            CP_WAIT0();         // V(i) done
        }
        __syncthreads();        // V visible to all

        // ---- acc += P^T' @ V via FFMA2 ----
#pragma unroll 4
        for (int n = 0; n < BN; ++n) {
            ulonglong2 pA = *(const ulonglong2*)(sPt + n * PS + (tm << 3));
            ulonglong2 pB = *(const ulonglong2*)(sPt + n * PS + (tm << 3) + 4);
            u64 p01 = pA.x, p23 = pA.y, p45 = pB.x, p67 = pB.y;
            float4 vf = *(const float4*)(sV + n * VS + (tn << 2));
            u64 v0 = pk2(vf.x, vf.x), v1 = pk2(vf.y, vf.y);
            u64 v2 = pk2(vf.z, vf.z), v3 = pk2(vf.w, vf.w);
            acc[0][0] = ffma2(p01, v0, acc[0][0]);
            acc[0][1] = ffma2(p01, v1, acc[0][1]);
            acc[0][2] = ffma2(p01, v2, acc[0][2]);
            acc[0][3] = ffma2(p01, v3, acc[0][3]);
            acc[1][0] = ffma2(p23, v0, acc[1][0]);
            acc[1][1] = ffma2(p23, v1, acc[1][1]);
            acc[1][2] = ffma2(p23, v2, acc[1][2]);
            acc[1][3] = ffma2(p23, v3, acc[1][3]);
            acc[2][0] = ffma2(p45, v0, acc[2][0]);
            acc[2][1] = ffma2(p45, v1, acc[2][1]);
            acc[2][2] = ffma2(p45, v2, acc[2][2]);
            acc[3][0] = ffma2(p67, v0, acc[3][0]);
            acc[2][3] = ffma2(p45, v3, acc[2][3]);
            acc[3][1] = ffma2(p67, v1, acc[3][1]);
            acc[3][2] = ffma2(p67, v2, acc[3][2]);
            acc[3][3] = ffma2(p67, v3, acc[3][3]);
        }
    }

    // ---- epilogue: out = acc / (l * 0.7) ----
#pragma unroll
    for (int ip = 0; ip < 4; ++ip) {
        float inv0 = 1.0f / (l_i[2 * ip] * 0.7f);
        float inv1 = 1.0f / (l_i[2 * ip + 1] * 0.7f);
        float lo[4], hi[4];
#pragma unroll
        for (int j = 0; j < 4; ++j) upk2(acc[ip][j], lo[j], hi[j]);
        int r0 = q0 + (tm << 3) + 2 * ip;
        float* o0 = out + ((size_t)b * SQ + r0) * Dd + (tn << 2);
        float* o1 = o0 + Dd;
        *(float4*)o0 = make_float4(lo[0] * inv0, lo[1] * inv0, lo[2] * inv0, lo[3] * inv0);
        *(float4*)o1 = make_float4(hi[0] * inv1, hi[1] * inv1, hi[2] * inv1, hi[3] * inv1);
    }
}

// ---------------------------------------------------------------------------
extern "C" void kernel_launch(void* const* d_in, const int* in_sizes, int n_in,
                              void* d_out, int out_size) {
    const float* q  = (const float*)d_in[0];
    const float* k  = (const float*)d_in[1];
    const float* v  = (const float*)d_in[2];
    const float* sf = (const float*)d_in[3];
    float* out = (float*)d_out;

    // 1) K -> g_kt transpose  [B][D][SKV]
    {
        dim3 grid(SKV / 32, Dd / 32, Bz);
        transpose_k_kernel<<<grid, dim3(32, 8)>>>(k);
    }

    // 2) Flash attention
    size_t smem_bytes = (size_t)(Dd * QS + Dd * KS + BN * VS + BN * PS) * 4;
    cudaFuncSetAttribute(attn_kernel, cudaFuncAttributeMaxDynamicSharedMemorySize,
                         (int)smem_bytes);
    dim3 grid(SQ / BM, Bz);
    attn_kernel<<<grid, NT, smem_bytes>>>(q, v, sf, out);
}